// round 1
// baseline (speedup 1.0000x reference)
#include <cuda_runtime.h>
#include <math.h>
#include <stdint.h>

#define NB 64
#define NP 8732
#define NO 12
#define NC 81
#define ROWW 85
#define JT 0.5f

// -------- scratch (device globals: allowed; no allocations) --------
__device__ float g_loss_l;
__device__ float g_ce_pos;
__device__ float g_ce_topk;
__device__ int   g_numpos[NB];
__device__ int   g_conf[NB * NP];
__device__ float g_ceneg[NB * NP];

__global__ void init_kernel() {
    g_loss_l = 0.f;
    g_ce_pos = 0.f;
    g_ce_topk = 0.f;
}

__device__ __forceinline__ float sl1(float d) {
    float ad = fabsf(d);
    return ad < 1.f ? 0.5f * d * d : ad - 0.5f;
}

// ---------------- kernel 1: matching + localization loss ----------------
__global__ void __launch_bounds__(256) match_kernel(
    const float* __restrict__ pred,
    const float* __restrict__ truths,   // (B, O, 4) point form
    const int*   __restrict__ labels,   // (B, O)
    const float* __restrict__ dbox)     // (P, 4) center form
{
    const int b = blockIdx.x;
    const int tid = threadIdx.x;

    __shared__ float4 s_t[NO];
    __shared__ float  s_area[NO];
    __shared__ int    s_lab[NO];
    __shared__ unsigned long long s_best[NO];
    __shared__ int    s_bp[NO];
    __shared__ float  s_ll;
    __shared__ int    s_np;

    if (tid < NO) {
        float4 t = ((const float4*)truths)[b * NO + tid];
        s_t[tid] = t;
        s_area[tid] = (t.z - t.x) * (t.w - t.y);
        s_lab[tid] = labels[b * NO + tid];
        s_best[tid] = 0ull;
    }
    if (tid == 0) { s_ll = 0.f; s_np = 0; }
    __syncthreads();

    // pass 1: per-truth argmax over priors (first-occurrence ties via ~p)
    unsigned long long lb[NO];
#pragma unroll
    for (int o = 0; o < NO; ++o) lb[o] = 0ull;

    const float4* db = (const float4*)dbox;
    for (int p = tid; p < NP; p += blockDim.x) {
        float4 d = db[p];
        float px0 = d.x - 0.5f * d.z, py0 = d.y - 0.5f * d.w;
        float px1 = d.x + 0.5f * d.z, py1 = d.y + 0.5f * d.w;
        float pa = d.z * d.w;
#pragma unroll
        for (int o = 0; o < NO; ++o) {
            float4 t = s_t[o];
            float ix = fmaxf(fminf(t.z, px1) - fmaxf(t.x, px0), 0.f);
            float iy = fmaxf(fminf(t.w, py1) - fmaxf(t.y, py0), 0.f);
            float inter = ix * iy;
            float iou = inter / (s_area[o] + pa - inter);
            unsigned long long key =
                ((unsigned long long)__float_as_uint(iou) << 32) | (unsigned)(~p);
            lb[o] = (key > lb[o]) ? key : lb[o];
        }
    }
#pragma unroll
    for (int o = 0; o < NO; ++o) atomicMax(&s_best[o], lb[o]);
    __syncthreads();
    if (tid < NO) s_bp[tid] = (int)(~(unsigned)(s_best[tid] & 0xFFFFFFFFull));
    __syncthreads();

    // pass 2: per-prior best truth, override, conf_t, loc loss
    float ll = 0.f;
    int np = 0;
    for (int p = tid; p < NP; p += blockDim.x) {
        float4 d = db[p];
        float px0 = d.x - 0.5f * d.z, py0 = d.y - 0.5f * d.w;
        float px1 = d.x + 0.5f * d.z, py1 = d.y + 0.5f * d.w;
        float pa = d.z * d.w;
        float bov = -1.f;
        int bi = 0;
#pragma unroll
        for (int o = 0; o < NO; ++o) {
            float4 t = s_t[o];
            float ix = fmaxf(fminf(t.z, px1) - fmaxf(t.x, px0), 0.f);
            float iy = fmaxf(fminf(t.w, py1) - fmaxf(t.y, py0), 0.f);
            float inter = ix * iy;
            float iou = inter / (s_area[o] + pa - inter);
            if (iou > bov) { bov = iou; bi = o; }   // first max wins (strict >)
        }
#pragma unroll
        for (int o = 0; o < NO; ++o)
            if (s_bp[o] == p) { bov = 2.f; bi = o; }  // last write wins

        int conf = (bov < JT) ? 0 : (s_lab[bi] + 1);
        g_conf[b * NP + p] = conf;

        if (conf > 0) {
            np++;
            float4 t = s_t[bi];
            float gx = ((t.x + t.z) * 0.5f - d.x) / (0.1f * d.z);
            float gy = ((t.y + t.w) * 0.5f - d.y) / (0.1f * d.w);
            float gw = logf((t.z - t.x) / d.z) / 0.2f;
            float gh = logf((t.w - t.y) / d.w) / 0.2f;
            const float* lp = pred + ((size_t)b * NP + p) * ROWW;
            ll += sl1(lp[0] - gx) + sl1(lp[1] - gy) +
                  sl1(lp[2] - gw) + sl1(lp[3] - gh);
        }
    }
#pragma unroll
    for (int off = 16; off; off >>= 1) {
        ll += __shfl_xor_sync(0xffffffffu, ll, off);
        np += __shfl_xor_sync(0xffffffffu, np, off);
    }
    if ((tid & 31) == 0) {
        atomicAdd(&s_ll, ll);
        atomicAdd(&s_np, np);
    }
    __syncthreads();
    if (tid == 0) {
        atomicAdd(&g_loss_l, s_ll);
        g_numpos[b] = s_np;
    }
}

// ---------------- kernel 2: cross-entropy per prior (warp/prior) ----------------
__global__ void __launch_bounds__(256) ce_kernel(const float* __restrict__ pred) {
    int w = (int)((blockIdx.x * (unsigned)blockDim.x + threadIdx.x) >> 5);
    int lane = threadIdx.x & 31;
    if (w >= NB * NP) return;

    const float* row = pred + (size_t)w * ROWW + 4;
    float x0 = row[lane];
    float x1 = row[32 + lane];
    float x2 = (lane < NC - 64) ? row[64 + lane] : -INFINITY;

    float m = fmaxf(x0, fmaxf(x1, x2));
#pragma unroll
    for (int off = 16; off; off >>= 1)
        m = fmaxf(m, __shfl_xor_sync(0xffffffffu, m, off));

    float e = expf(x0 - m) + expf(x1 - m) +
              ((lane < NC - 64) ? expf(x2 - m) : 0.f);
#pragma unroll
    for (int off = 16; off; off >>= 1)
        e += __shfl_xor_sync(0xffffffffu, e, off);

    float lse = m + logf(e);

    int t = g_conf[w];                 // tgt = clip(conf,0,80) == conf
    int r = t >> 5;
    float xs = (r == 0) ? x0 : ((r == 1) ? x1 : x2);
    float xt = __shfl_sync(0xffffffffu, xs, t & 31);

    if (lane == 0) {
        float ce = lse - xt;
        if (t > 0) {
            atomicAdd(&g_ce_pos, ce);
            g_ceneg[w] = 0.f;
        } else {
            g_ceneg[w] = ce;
        }
    }
}

// ---------------- kernel 3: per-batch exact top-k sum of ce_neg ----------------
__global__ void __launch_bounds__(256) topk_kernel() {
    const int b = blockIdx.x;
    const int tid = threadIdx.x;
    const int T = 256;

    __shared__ unsigned keys[NP];   // ~35 KB
    __shared__ int s_cnt;
    __shared__ float s_sum;

    for (int i = tid; i < NP; i += T)
        keys[i] = __float_as_uint(g_ceneg[b * NP + i]);   // all >= 0
    int k = g_numpos[b] * 3;
    if (k > NP) k = NP;
    __syncthreads();
    if (k <= 0) return;

    // bitwise descent: v = k-th largest key (largest v with count(>=v) >= k)
    unsigned v = 0;
    for (int bit = 30; bit >= 0; --bit) {
        unsigned trial = v | (1u << bit);
        int c = 0;
        for (int i = tid; i < NP; i += T) c += (keys[i] >= trial);
#pragma unroll
        for (int off = 16; off; off >>= 1)
            c += __shfl_xor_sync(0xffffffffu, c, off);
        if (tid == 0) s_cnt = 0;
        __syncthreads();
        if ((tid & 31) == 0) atomicAdd(&s_cnt, c);
        __syncthreads();
        if (s_cnt >= k) v = trial;
        __syncthreads();
    }

    // sum of strictly-greater keys + tie correction at v
    int cgt = 0;
    float sgt = 0.f;
    for (int i = tid; i < NP; i += T) {
        unsigned kk = keys[i];
        if (kk > v) { cgt++; sgt += __uint_as_float(kk); }
    }
#pragma unroll
    for (int off = 16; off; off >>= 1) {
        cgt += __shfl_xor_sync(0xffffffffu, cgt, off);
        sgt += __shfl_xor_sync(0xffffffffu, sgt, off);
    }
    if (tid == 0) { s_cnt = 0; s_sum = 0.f; }
    __syncthreads();
    if ((tid & 31) == 0) { atomicAdd(&s_cnt, cgt); atomicAdd(&s_sum, sgt); }
    __syncthreads();
    if (tid == 0) {
        float total = s_sum + (float)(k - s_cnt) * __uint_as_float(v);
        atomicAdd(&g_ce_topk, total);
    }
}

// ---------------- kernel 4: finalize ----------------
__global__ void finalize_kernel(float* __restrict__ out) {
    int N = 0;
    for (int b = 0; b < NB; ++b) N += g_numpos[b];
    float fN = (float)N;
    out[0] = g_loss_l / fN;
    out[1] = (g_ce_pos + g_ce_topk) / fN;
}

extern "C" void kernel_launch(void* const* d_in, const int* in_sizes, int n_in,
                              void* d_out, int out_size) {
    const float* pred   = (const float*)d_in[0];
    const float* truths = (const float*)d_in[1];
    const int*   labels = (const int*)d_in[2];
    const float* dbox   = (const float*)d_in[3];
    float* out = (float*)d_out;

    init_kernel<<<1, 1>>>();
    match_kernel<<<NB, 256>>>(pred, truths, labels, dbox);

    const long long total_threads = (long long)NB * NP * 32;
    const int blocks = (int)((total_threads + 255) / 256);
    ce_kernel<<<blocks, 256>>>(pred);

    topk_kernel<<<NB, 256>>>();
    finalize_kernel<<<1, 1>>>(out);
}

// round 3
// speedup vs baseline: 3.1111x; 3.1111x over previous
#include <cuda_runtime.h>
#include <math.h>
#include <stdint.h>

#define NB 64
#define NP 8732
#define NO 12
#define NC 81
#define ROWW 85
#define JT 0.5f
#define CHUNK 2183        // NP / 4

// -------- scratch (device globals) --------
__device__ float g_loss_l;
__device__ float g_ce_pos;
__device__ float g_ce_topk;
__device__ int   g_numpos[NB];
__device__ unsigned long long g_best[NB * NO];
__device__ int   g_conf[NB * NP];
__device__ float g_ceneg[NB * NP];

__global__ void init_kernel() {
    int tid = threadIdx.x;
    if (tid == 0) { g_loss_l = 0.f; g_ce_pos = 0.f; g_ce_topk = 0.f; }
    for (int i = tid; i < NB; i += blockDim.x) g_numpos[i] = 0;
    for (int i = tid; i < NB * NO; i += blockDim.x) g_best[i] = 0ull;
}

__device__ __forceinline__ float sl1(float d) {
    float ad = fabsf(d);
    return ad < 1.f ? 0.5f * d * d : ad - 0.5f;
}

__device__ __forceinline__ float iou_fast(float4 t, float ta,
                                          float px0, float py0, float px1, float py1,
                                          float pa) {
    float ix = fmaxf(fminf(t.z, px1) - fmaxf(t.x, px0), 0.f);
    float iy = fmaxf(fminf(t.w, py1) - fmaxf(t.y, py0), 0.f);
    float inter = ix * iy;
    return __fdividef(inter, ta + pa - inter);
}

// ---------------- match pass 1: per-truth best prior ----------------
__global__ void __launch_bounds__(256) match1_kernel(
    const float* __restrict__ truths, const float* __restrict__ dbox)
{
    const int chunk = blockIdx.x;
    const int b = blockIdx.y;
    const int tid = threadIdx.x;

    __shared__ float4 s_t[NO];
    __shared__ float  s_area[NO];
    __shared__ unsigned long long s_best[NO];

    if (tid < NO) {
        float4 t = ((const float4*)truths)[b * NO + tid];
        s_t[tid] = t;
        s_area[tid] = (t.z - t.x) * (t.w - t.y);
        s_best[tid] = 0ull;
    }
    __syncthreads();

    unsigned long long lb[NO];
#pragma unroll
    for (int o = 0; o < NO; ++o) lb[o] = 0ull;

    const float4* db = (const float4*)dbox;
    const int pend = (chunk + 1) * CHUNK;
    for (int p = chunk * CHUNK + tid; p < pend; p += 256) {
        float4 d = db[p];
        float px0 = d.x - 0.5f * d.z, py0 = d.y - 0.5f * d.w;
        float px1 = d.x + 0.5f * d.z, py1 = d.y + 0.5f * d.w;
        float pa = d.z * d.w;
#pragma unroll
        for (int o = 0; o < NO; ++o) {
            float iou = iou_fast(s_t[o], s_area[o], px0, py0, px1, py1, pa);
            unsigned long long key =
                ((unsigned long long)__float_as_uint(iou) << 32) | (unsigned)(~p);
            lb[o] = (key > lb[o]) ? key : lb[o];
        }
    }
#pragma unroll
    for (int o = 0; o < NO; ++o) atomicMax(&s_best[o], lb[o]);
    __syncthreads();
    if (tid < NO) atomicMax(&g_best[b * NO + tid], s_best[tid]);
}

// ---------------- match pass 2: conf_t + loc loss ----------------
__global__ void __launch_bounds__(256) match2_kernel(
    const float* __restrict__ pred,
    const float* __restrict__ truths,
    const int*   __restrict__ labels,
    const float* __restrict__ dbox)
{
    const int chunk = blockIdx.x;
    const int b = blockIdx.y;
    const int tid = threadIdx.x;

    __shared__ float4 s_t[NO];
    __shared__ float  s_area[NO];
    __shared__ int    s_lab[NO];
    __shared__ int    s_bp[NO];
    __shared__ float  s_ll;
    __shared__ int    s_np;

    if (tid < NO) {
        float4 t = ((const float4*)truths)[b * NO + tid];
        s_t[tid] = t;
        s_area[tid] = (t.z - t.x) * (t.w - t.y);
        s_lab[tid] = labels[b * NO + tid];
        s_bp[tid] = (int)(~(unsigned)(g_best[b * NO + tid] & 0xFFFFFFFFull));
    }
    if (tid == 0) { s_ll = 0.f; s_np = 0; }
    __syncthreads();

    const float4* db = (const float4*)dbox;
    float ll = 0.f;
    int np = 0;
    const int pend = (chunk + 1) * CHUNK;
    for (int p = chunk * CHUNK + tid; p < pend; p += 256) {
        float4 d = db[p];
        float px0 = d.x - 0.5f * d.z, py0 = d.y - 0.5f * d.w;
        float px1 = d.x + 0.5f * d.z, py1 = d.y + 0.5f * d.w;
        float pa = d.z * d.w;
        float bov = -1.f;
        int bi = 0;
#pragma unroll
        for (int o = 0; o < NO; ++o) {
            float iou = iou_fast(s_t[o], s_area[o], px0, py0, px1, py1, pa);
            if (iou > bov) { bov = iou; bi = o; }   // first max wins
        }
#pragma unroll
        for (int o = 0; o < NO; ++o)
            if (s_bp[o] == p) { bov = 2.f; bi = o; }   // last write wins

        int conf = (bov < JT) ? 0 : (s_lab[bi] + 1);
        g_conf[b * NP + p] = conf;

        if (conf > 0) {
            np++;
            float4 t = s_t[bi];
            float gx = ((t.x + t.z) * 0.5f - d.x) * __fdividef(1.f, 0.1f * d.z);
            float gy = ((t.y + t.w) * 0.5f - d.y) * __fdividef(1.f, 0.1f * d.w);
            float gw = __logf(__fdividef(t.z - t.x, d.z)) * 5.0f;
            float gh = __logf(__fdividef(t.w - t.y, d.w)) * 5.0f;
            const float* lp = pred + ((size_t)b * NP + p) * ROWW;
            ll += sl1(lp[0] - gx) + sl1(lp[1] - gy) +
                  sl1(lp[2] - gw) + sl1(lp[3] - gh);
        }
    }
#pragma unroll
    for (int off = 16; off; off >>= 1) {
        ll += __shfl_xor_sync(0xffffffffu, ll, off);
        np += __shfl_xor_sync(0xffffffffu, np, off);
    }
    if ((tid & 31) == 0) { atomicAdd(&s_ll, ll); atomicAdd(&s_np, np); }
    __syncthreads();
    if (tid == 0) {
        atomicAdd(&g_loss_l, s_ll);
        atomicAdd(&g_numpos[b], s_np);
    }
}

// ---------------- CE: 8 lanes per prior, fast exp/log ----------------
__global__ void __launch_bounds__(256) ce_kernel(const float* __restrict__ pred) {
    const int warp = (int)((blockIdx.x * 256u + threadIdx.x) >> 5);
    const int lane = threadIdx.x & 31;
    const int sub = lane & 7;                 // position within 8-lane group
    const int pr = warp * 4 + (lane >> 3);    // prior handled by this group

    const int t = g_conf[pr];                 // issue early: independent chain
    const float* row = pred + (size_t)pr * ROWW + 4;
    const float xt = __ldg(row + t);          // tgt logit (conf in [0,80])

    float x[11];
    float m = -INFINITY;
#pragma unroll
    for (int j = 0; j < 10; ++j) {            // indices 0..79: always valid
        x[j] = __ldg(row + j * 8 + sub);
        m = fmaxf(m, x[j]);
    }
    x[10] = (sub == 0) ? __ldg(row + 80) : -INFINITY;
    m = fmaxf(m, x[10]);

    m = fmaxf(m, __shfl_xor_sync(0xffffffffu, m, 4));
    m = fmaxf(m, __shfl_xor_sync(0xffffffffu, m, 2));
    m = fmaxf(m, __shfl_xor_sync(0xffffffffu, m, 1));

    float e = 0.f;
#pragma unroll
    for (int j = 0; j < 11; ++j)
        e += __expf(x[j] - m);                // exp(-inf) -> 0
    e += __shfl_xor_sync(0xffffffffu, e, 4);
    e += __shfl_xor_sync(0xffffffffu, e, 2);
    e += __shfl_xor_sync(0xffffffffu, e, 1);

    if (sub == 0) {
        float ce = m + __logf(e) - xt;
        if (t > 0) {
            atomicAdd(&g_ce_pos, ce);
            g_ceneg[pr] = 0.f;
        } else {
            g_ceneg[pr] = ce;
        }
    }
}

// ---------------- per-batch top-k sum via MSD radix-256 select ----------------
__global__ void __launch_bounds__(256) topk_kernel() {
    const int b = blockIdx.x;
    const int tid = threadIdx.x;

    __shared__ unsigned keys[NP];             // ~35 KB
    __shared__ int  hist[256];
    __shared__ unsigned s_v;
    __shared__ int  s_k;
    __shared__ int  s_cnt;
    __shared__ float s_sum;

    for (int i = tid; i < NP; i += 256)
        keys[i] = __float_as_uint(g_ceneg[b * NP + i]);   // all >= 0
    int k0 = g_numpos[b] * 3;
    if (k0 > NP) k0 = NP;
    __syncthreads();
    if (k0 <= 0) return;

    unsigned v = 0;
    int kk = k0;
    for (int shift = 24; shift >= 0; shift -= 8) {
        hist[tid] = 0;
        __syncthreads();
        const unsigned prefmask = (shift == 24) ? 0u : (0xFFFFFFFFu << (shift + 8));
        for (int i = tid; i < NP; i += 256) {
            unsigned kv = keys[i];
            if ((kv & prefmask) == v)
                atomicAdd(&hist[(kv >> shift) & 255], 1);
        }
        __syncthreads();
        if (tid == 0) {
            int cum = 0;
            int byte = 0;
            for (int bb = 255; bb >= 0; --bb) {
                int c = hist[bb];
                if (cum + c >= kk) { byte = bb; kk -= cum; break; }
                cum += c;
            }
            s_v = v | ((unsigned)byte << shift);
            s_k = kk;
        }
        __syncthreads();
        v = s_v; kk = s_k;
        __syncthreads();
    }

    // v = exact k-th largest key; sum strictly-greater + tie correction
    int cgt = 0;
    float sgt = 0.f;
    for (int i = tid; i < NP; i += 256) {
        unsigned kv = keys[i];
        if (kv > v) { cgt++; sgt += __uint_as_float(kv); }
    }
#pragma unroll
    for (int off = 16; off; off >>= 1) {
        cgt += __shfl_xor_sync(0xffffffffu, cgt, off);
        sgt += __shfl_xor_sync(0xffffffffu, sgt, off);
    }
    if (tid == 0) { s_cnt = 0; s_sum = 0.f; }
    __syncthreads();
    if ((tid & 31) == 0) { atomicAdd(&s_cnt, cgt); atomicAdd(&s_sum, sgt); }
    __syncthreads();
    if (tid == 0) {
        float total = s_sum + (float)(k0 - s_cnt) * __uint_as_float(v);
        atomicAdd(&g_ce_topk, total);
    }
}

// ---------------- finalize ----------------
__global__ void finalize_kernel(float* __restrict__ out) {
    int N = 0;
    for (int b = 0; b < NB; ++b) N += g_numpos[b];
    float fN = (float)N;
    out[0] = g_loss_l / fN;
    out[1] = (g_ce_pos + g_ce_topk) / fN;
}

extern "C" void kernel_launch(void* const* d_in, const int* in_sizes, int n_in,
                              void* d_out, int out_size) {
    const float* pred   = (const float*)d_in[0];
    const float* truths = (const float*)d_in[1];
    const int*   labels = (const int*)d_in[2];
    const float* dbox   = (const float*)d_in[3];
    float* out = (float*)d_out;

    init_kernel<<<1, 256>>>();

    dim3 mgrid(4, NB);
    match1_kernel<<<mgrid, 256>>>(truths, dbox);
    match2_kernel<<<mgrid, 256>>>(pred, truths, labels, dbox);

    // NB*NP = 558848 priors, 4 priors per warp, 8 warps per block
    const int ce_blocks = (NB * NP) / (4 * 8);   // 17464
    ce_kernel<<<ce_blocks, 256>>>(pred);

    topk_kernel<<<NB, 256>>>();
    finalize_kernel<<<1, 1>>>(out);
}